// round 1
// baseline (speedup 1.0000x reference)
#include <cuda_runtime.h>

// x:   [B=2, 1, D=64, H=256, W=256] fp32
// out: [B=2, 16, D=64, H=256, W=256] fp32
//   channel c even -> sobel magnitude of x slice, c odd -> x
//
// Pure HBM-write-bound: 32 MiB in, 512 MiB out. Compute sobel once per
// pixel, fan out 16 float4 streaming stores per thread (4 pixels/thread).

#define W 256
#define H 256
#define DD 64
#define B 2

__global__ __launch_bounds__(256) void sobel_cat_kernel(
    const float* __restrict__ x, float* __restrict__ out)
{
    // one thread = 4 consecutive w positions (one float4)
    int t   = blockIdx.x * blockDim.x + threadIdx.x;
    int wq  = t & 63;          // which float4 within the row (W/4 = 64)
    int row = t >> 6;          // global row index = (b*D + d)*H + h
    int h   = row & (H - 1);
    int bd  = row >> 8;        // b*D + d
    int w0  = wq << 2;

    const float* base = x + ((size_t)bd * H + h) * W;

    // Load the 3x6 neighborhood (w0-1 .. w0+4) with zero padding.
    float r0[6], r1[6], r2[6];
#pragma unroll
    for (int j = 0; j < 6; j++) {
        int w = w0 + j - 1;
        bool okw = (unsigned)w < (unsigned)W;
        r0[j] = (okw && h > 0)     ? __ldg(base + w - W) : 0.0f;
        r1[j] =  okw               ? __ldg(base + w)     : 0.0f;
        r2[j] = (okw && h < H - 1) ? __ldg(base + w + W) : 0.0f;
    }

    float4 sv, xv;
    float* s  = reinterpret_cast<float*>(&sv);
    float* xc = reinterpret_cast<float*>(&xv);
#pragma unroll
    for (int i = 0; i < 4; i++) {
        // cross-correlation with kx=[[-1,0,1],[-2,0,2],[-1,0,1]], ky=kx^T
        float gx = (r0[i + 2] - r0[i]) + 2.0f * (r1[i + 2] - r1[i]) + (r2[i + 2] - r2[i]);
        float gy = (r2[i]     - r0[i]) + 2.0f * (r2[i + 1] - r0[i + 1]) + (r2[i + 2] - r0[i + 2]);
        s[i]  = sqrtf(gx * gx + gy * gy);
        xc[i] = r1[i + 1];
    }

    int b = bd >> 6;          // bd / D
    int d = bd & (DD - 1);    // bd % D
    const size_t cstride = (size_t)DD * H * W;   // per-channel stride in elems
    float* obase = out
        + ((size_t)b * 16 * DD + d) * H * W
        + (size_t)h * W + w0;

#pragma unroll
    for (int c = 0; c < 16; c++) {
        float4 v = (c & 1) ? xv : sv;
        __stcs(reinterpret_cast<float4*>(obase + (size_t)c * cstride), v);
    }
}

extern "C" void kernel_launch(void* const* d_in, const int* in_sizes, int n_in,
                              void* d_out, int out_size)
{
    const float* x = (const float*)d_in[0];
    float* out = (float*)d_out;

    // total float4 groups = B*D*H*(W/4) = 2*64*256*64 = 2,097,152
    const int total = B * DD * H * (W / 4);
    const int threads = 256;
    const int blocks = total / threads;   // 8192
    sobel_cat_kernel<<<blocks, threads>>>(x, out);
}